// round 14
// baseline (speedup 1.0000x reference)
#include <cuda_runtime.h>
#include <cuda_bf16.h>
#include <mma.h>
#include <cstdint>

using namespace nvcuda;

#define MTOK 16384
#define NROW 3072
#define KDIM 1024

// ---- static device scratch (no allocations) ----
__device__ float         g_qkv[16 * 4 * 192 * 4096];   // [(h*4+b)*192 + j][s] (v rows only now)
__device__ __nv_bfloat16 g_Wh[NROW * KDIM], g_Wl[NROW * KDIM];
__device__ __nv_bfloat16 g_Xh[(size_t)MTOK * KDIM], g_Xl[(size_t)MTOK * KDIM];
__device__ __nv_bfloat16 g_qkh[(size_t)64 * 128 * 4096];  // [hb*128+jj][s] bf16 hi (q,k rows)
__device__ __nv_bfloat16 g_qkl[(size_t)64 * 128 * 4096];  // bf16 lo
__device__ float         g_part[8 * 64 * 64 * 64];     // [chunk][hb][d][e] (4 used)
__device__ float         g_probs[64 * 64 * 64];        // [hb][d][e]

// ============================ split fp32 -> bf16 hi/lo (float4 vectorized) ============================
__global__ void split_x(const float* __restrict__ s) {
    int idx = blockIdx.x * blockDim.x + threadIdx.x;
    float4 v = ((const float4*)s)[idx];
    __nv_bfloat162 h0 = __floats2bfloat162_rn(v.x, v.y);
    __nv_bfloat162 h1 = __floats2bfloat162_rn(v.z, v.w);
    ((__nv_bfloat162*)g_Xh)[idx * 2] = h0;
    ((__nv_bfloat162*)g_Xh)[idx * 2 + 1] = h1;
    __nv_bfloat162 l0 = __floats2bfloat162_rn(v.x - __low2float(h0), v.y - __high2float(h0));
    __nv_bfloat162 l1 = __floats2bfloat162_rn(v.z - __low2float(h1), v.w - __high2float(h1));
    ((__nv_bfloat162*)g_Xl)[idx * 2] = l0;
    ((__nv_bfloat162*)g_Xl)[idx * 2 + 1] = l1;
}
__global__ void split_w(const float* __restrict__ s) {
    int idx = blockIdx.x * blockDim.x + threadIdx.x;
    float4 v = ((const float4*)s)[idx];
    __nv_bfloat162 h0 = __floats2bfloat162_rn(v.x, v.y);
    __nv_bfloat162 h1 = __floats2bfloat162_rn(v.z, v.w);
    ((__nv_bfloat162*)g_Wh)[idx * 2] = h0;
    ((__nv_bfloat162*)g_Wh)[idx * 2 + 1] = h1;
    __nv_bfloat162 l0 = __floats2bfloat162_rn(v.x - __low2float(h0), v.y - __high2float(h0));
    __nv_bfloat162 l1 = __floats2bfloat162_rn(v.z - __low2float(h1), v.w - __high2float(h1));
    ((__nv_bfloat162*)g_Wl)[idx * 2] = l0;
    ((__nv_bfloat162*)g_Wl)[idx * 2 + 1] = l1;
}

// ============================ cp.async helpers ============================
__device__ __forceinline__ void cp16(void* dst, const void* src) {
    unsigned u = (unsigned)__cvta_generic_to_shared(dst);
    asm volatile("cp.async.cg.shared.global [%0], [%1], 16;\n" ::"r"(u), "l"(src));
}
__device__ __forceinline__ void cp_commit() { asm volatile("cp.async.commit_group;\n"); }
template <int N> __device__ __forceinline__ void cp_wait() {
    asm volatile("cp.async.wait_group %0;\n" ::"n"(N));
}

typedef wmma::fragment<wmma::matrix_a, 16, 16, 16, __nv_bfloat16, wmma::row_major> FragA;
typedef wmma::fragment<wmma::matrix_b, 16, 16, 16, __nv_bfloat16, wmma::col_major> FragB;
typedef wmma::fragment<wmma::accumulator, 16, 16, 16, float> FragC;

// ============================ QKV GEMM (R9-proven mainloop; epilogue: q,k -> bf16 hi/lo) ============================
#define LDM  24
#define STG  24576
#define NSTG 4

__global__ __launch_bounds__(256, 2) void qkv_gemm(const float* __restrict__ bias) {
    extern __shared__ char smem[];
    const int t = threadIdx.x;
    const int m0 = blockIdx.y * 128;
    const int tok0 = blockIdx.x * 128;

    const int row = t >> 1, half = t & 1;
    const int soff = row * LDM + half * 8;
    const size_t gA = (size_t)(m0 + row) * KDIM + half * 8;
    const size_t gB = (size_t)(tok0 + row) * KDIM + half * 8;

    auto load_stage = [&](int slot, int kt) {
        char* base = smem + slot * STG;
        const int k0 = kt * 16;
        cp16((__nv_bfloat16*)(base) + soff,         g_Wh + gA + k0);
        cp16((__nv_bfloat16*)(base + 6144) + soff,  g_Wl + gA + k0);
        cp16((__nv_bfloat16*)(base + 12288) + soff, g_Xh + gB + k0);
        cp16((__nv_bfloat16*)(base + 18432) + soff, g_Xl + gB + k0);
    };

    FragC acc[2][4];
#pragma unroll
    for (int i = 0; i < 2; i++)
#pragma unroll
        for (int j = 0; j < 4; j++) wmma::fill_fragment(acc[i][j], 0.0f);

    load_stage(0, 0); cp_commit();
    load_stage(1, 1); cp_commit();
    load_stage(2, 2); cp_commit();

    const int wid = t >> 5, lane = t & 31;
    const int wm = wid >> 1, wn = wid & 1;

    for (int kt = 0; kt < 64; kt++) {
        cp_wait<2>();
        __syncthreads();
        if (kt + 3 < 64) load_stage((kt + 3) & 3, kt + 3);
        cp_commit();

        char* base = smem + (kt & 3) * STG;
        __nv_bfloat16* sAh = (__nv_bfloat16*)(base);
        __nv_bfloat16* sAl = (__nv_bfloat16*)(base + 6144);
        __nv_bfloat16* sBh = (__nv_bfloat16*)(base + 12288);
        __nv_bfloat16* sBl = (__nv_bfloat16*)(base + 18432);

        FragA ah[2], al[2];
#pragma unroll
        for (int i = 0; i < 2; i++) {
            wmma::load_matrix_sync(ah[i], sAh + (wm * 32 + i * 16) * LDM, LDM);
            wmma::load_matrix_sync(al[i], sAl + (wm * 32 + i * 16) * LDM, LDM);
        }
#pragma unroll
        for (int j = 0; j < 4; j++) {
            FragB bh, bl;
            wmma::load_matrix_sync(bh, sBh + (wn * 64 + j * 16) * LDM, LDM);
            wmma::load_matrix_sync(bl, sBl + (wn * 64 + j * 16) * LDM, LDM);
            wmma::mma_sync(acc[0][j], ah[0], bh, acc[0][j]);
            wmma::mma_sync(acc[1][j], ah[1], bh, acc[1][j]);
            wmma::mma_sync(acc[0][j], ah[0], bl, acc[0][j]);
            wmma::mma_sync(acc[1][j], ah[1], bl, acc[1][j]);
            wmma::mma_sync(acc[0][j], al[0], bh, acc[0][j]);
            wmma::mma_sync(acc[1][j], al[1], bh, acc[1][j]);
        }
    }
    cp_wait<0>();
    __syncthreads();

    // ---- epilogue: bias + fused RoPE; q,k rows -> bf16 hi/lo, v rows -> fp32 ----
    float* sStage = (float*)smem + wid * 256;
    const int bidx = tok0 >> 12, sin = tok0 & 4095;
#pragma unroll
    for (int i = 0; i < 2; i++)
#pragma unroll
        for (int j = 0; j < 4; j++) {
            wmma::store_matrix_sync(sStage, acc[i][j], 16, wmma::mem_row_major);
            __syncwarp();
            const int m = m0 + wm * 32 + i * 16 + (lane >> 1);
            const int h = m / 192, jj = m % 192;
            const int s = sin + wn * 64 + j * 16 + ((lane & 1) << 3);
            const float bv = bias[m];
            const float* src = sStage + (lane >> 1) * 16 + ((lane & 1) << 3);
            float4 v0 = *(const float4*)src;
            float4 v1 = *(const float4*)(src + 4);
            v0.x += bv; v0.y += bv; v0.z += bv; v0.w += bv;
            v1.x += bv; v1.y += bv; v1.z += bv; v1.w += bv;
            if (sin == 0 && wn == 0 && j < 2 && jj < 128) {
                const int d = jj & 63;
                const int ibase = (j * 16 + ((lane & 1) << 3)) >> 1;
#pragma unroll
                for (int pr = 0; pr < 4; pr++) {
                    int ii = ibase + pr;
                    float inv = expf(-((float)(2 * ii) / 32.0f) * 9.210340371976184f);
                    float ang = (float)d * inv;
                    float sv, cv;
                    sincosf(ang, &sv, &cv);
                    float* pe = (pr < 2) ? ((float*)&v0 + pr * 2) : ((float*)&v1 + (pr - 2) * 2);
                    float a0 = pe[0], a1 = pe[1];
                    pe[0] = a0 * cv - a1 * sv;
                    pe[1] = a1 * cv + a0 * sv;
                }
            }
            if (jj < 128) {
                // split to bf16 hi/lo for tensor-core scores
                const size_t qk = (size_t)((h * 4 + bidx) * 128 + jj) * 4096 + s;
                float vv[8] = {v0.x, v0.y, v0.z, v0.w, v1.x, v1.y, v1.z, v1.w};
                alignas(16) __nv_bfloat16 hh[8];
                alignas(16) __nv_bfloat16 ll[8];
#pragma unroll
                for (int e = 0; e < 8; e++) {
                    hh[e] = __float2bfloat16(vv[e]);
                    ll[e] = __float2bfloat16(vv[e] - __bfloat162float(hh[e]));
                }
                *(uint4*)(g_qkh + qk) = *(const uint4*)hh;
                *(uint4*)(g_qkl + qk) = *(const uint4*)ll;
            } else {
                float* dst = g_qkv + (size_t)((h * 4 + bidx) * 192 + jj) * 4096 + s;
                *(float4*)dst = v0;
                *(float4*)(dst + 4) = v1;
            }
            __syncwarp();
        }
}

// ============================ scores via tensor cores ============================
// g_part[cc][hb][d][e] = 0.125 * sum_{s in chunk cc} q[d][s]*k[e][s], 3-term split-bf16.
// grid (4, 64): chunk cc (1024 s), hb. 8 warps: warp w -> row-tile wi=w>>1,
// col-tiles wj0=(w&1)*2, wj0+1. Fragments loaded directly from gmem (L1-shared).
__global__ __launch_bounds__(256) void scores_tc() {
    const int hb = blockIdx.y, cc = blockIdx.x;
    const int w = threadIdx.x >> 5;
    const int wi = w >> 1, wj0 = (w & 1) * 2;

    const size_t qrow = (size_t)(hb * 128 + wi * 16) * 4096 + cc * 1024;
    const size_t krow0 = (size_t)(hb * 128 + 64 + wj0 * 16) * 4096 + cc * 1024;
    const size_t krow1 = krow0 + (size_t)16 * 4096;

    FragC a0, a1;
    wmma::fill_fragment(a0, 0.0f);
    wmma::fill_fragment(a1, 0.0f);

    for (int ks = 0; ks < 64; ks++) {
        const int o = ks * 16;
        FragA qh, ql;
        FragB kh0, kl0, kh1, kl1;
        wmma::load_matrix_sync(qh, g_qkh + qrow + o, 4096);
        wmma::load_matrix_sync(ql, g_qkl + qrow + o, 4096);
        wmma::load_matrix_sync(kh0, g_qkh + krow0 + o, 4096);
        wmma::load_matrix_sync(kl0, g_qkl + krow0 + o, 4096);
        wmma::load_matrix_sync(kh1, g_qkh + krow1 + o, 4096);
        wmma::load_matrix_sync(kl1, g_qkl + krow1 + o, 4096);
        wmma::mma_sync(a0, qh, kh0, a0);
        wmma::mma_sync(a1, qh, kh1, a1);
        wmma::mma_sync(a0, qh, kl0, a0);
        wmma::mma_sync(a1, qh, kl1, a1);
        wmma::mma_sync(a0, ql, kh0, a0);
        wmma::mma_sync(a1, ql, kh1, a1);
    }
#pragma unroll
    for (int e = 0; e < a0.num_elements; e++) { a0.x[e] *= 0.125f; a1.x[e] *= 0.125f; }

    float* base = g_part + ((size_t)(cc * 64 + hb) * 64 + wi * 16) * 64;
    wmma::store_matrix_sync(base + wj0 * 16, a0, 64, wmma::mem_row_major);
    wmma::store_matrix_sync(base + (wj0 + 1) * 16, a1, 64, wmma::mem_row_major);
}

// ============================ softmax (4 chunks) ============================
__global__ __launch_bounds__(256) void softmax_kernel() {
    int w = threadIdx.x >> 5, lane = threadIdx.x & 31;
    int r = blockIdx.x * 8 + w;  // 0..4095
    int hb = r >> 6, d = r & 63;
    float v0 = 0.f, v1 = 0.f;
#pragma unroll
    for (int c = 0; c < 4; c++) {
        const float* p = g_part + ((size_t)(c * 64 + hb) * 64 + d) * 64;
        v0 += p[lane];
        v1 += p[lane + 32];
    }
    float m = fmaxf(v0, v1);
#pragma unroll
    for (int o = 16; o > 0; o >>= 1) m = fmaxf(m, __shfl_xor_sync(0xffffffffu, m, o));
    float p0 = expf(v0 - m), p1 = expf(v1 - m);
    float sum = p0 + p1;
#pragma unroll
    for (int o = 16; o > 0; o >>= 1) sum += __shfl_xor_sync(0xffffffffu, sum, o);
    float inv = 1.0f / sum;
    float* dst = g_probs + (size_t)r * 64;
    dst[lane] = p0 * inv;
    dst[lane + 32] = p1 * inv;
}

// ============================ out GEMM (2 s-columns per thread) ============================
__global__ __launch_bounds__(256) void out_kernel(float* __restrict__ out) {
    __shared__ float sP[64 * 64];
    int hb = blockIdx.y, t = threadIdx.x;
#pragma unroll
    for (int i = 0; i < 16; i++) sP[t + 256 * i] = g_probs[(size_t)hb * 4096 + t + 256 * i];
    __syncthreads();
    int s = blockIdx.x * 256 + (t & 127);
    int dh = t >> 7;
    const float* v = g_qkv + (size_t)(hb * 192 + 128) * 4096;
    float accA[32] = {}, accB[32] = {};
    for (int e = 0; e < 64; e += 4) {
        float a0 = v[(size_t)e * 4096 + s];
        float a1 = v[(size_t)(e + 1) * 4096 + s];
        float a2 = v[(size_t)(e + 2) * 4096 + s];
        float a3 = v[(size_t)(e + 3) * 4096 + s];
        float b0 = v[(size_t)e * 4096 + s + 128];
        float b1 = v[(size_t)(e + 1) * 4096 + s + 128];
        float b2 = v[(size_t)(e + 2) * 4096 + s + 128];
        float b3 = v[(size_t)(e + 3) * 4096 + s + 128];
#pragma unroll
        for (int d = 0; d < 32; d++) {
            const float4 p = *(const float4*)&sP[(dh * 32 + d) * 64 + e];
            accA[d] += p.x * a0 + p.y * a1 + p.z * a2 + p.w * a3;
            accB[d] += p.x * b0 + p.y * b1 + p.z * b2 + p.w * b3;
        }
    }
    int h = hb >> 2, b = hb & 3;
#pragma unroll
    for (int d = 0; d < 32; d++) {
        int dd = dh * 32 + d;
        size_t o = (size_t)((h * 64 + dd) * 4 + b) * 4096 + s;
        out[o] = accA[d];
        out[o + 128] = accB[d];
    }
}

extern "C" void kernel_launch(void* const* d_in, const int* in_sizes, int n_in,
                              void* d_out, int out_size) {
    const float* x = (const float*)d_in[0];
    const float* W = (const float*)d_in[1];
    const float* bias = (const float*)d_in[2];
    float* out = (float*)d_out;

    cudaFuncSetAttribute(qkv_gemm, cudaFuncAttributeMaxDynamicSharedMemorySize, NSTG * STG);

    split_x<<<16384, 256>>>(x);                            // idx 0
    split_w<<<3072, 256>>>(W);                             // idx 1
    qkv_gemm<<<dim3(128, 24), 256, NSTG * STG>>>(bias);    // idx 2
    scores_tc<<<dim3(4, 64), 256>>>();                     // idx 3 <- ncu capture slot
    softmax_kernel<<<512, 256>>>();
    out_kernel<<<dim3(16, 64), 256>>>(out);
}

// round 16
// speedup vs baseline: 1.0622x; 1.0622x over previous
#include <cuda_runtime.h>
#include <cuda_bf16.h>
#include <mma.h>
#include <cstdint>

using namespace nvcuda;

#define MTOK 16384
#define NROW 3072
#define KDIM 1024

// ---- static device scratch (no allocations) ----
__device__ float         g_qkv[16 * 4 * 192 * 4096];   // [(h*4+b)*192 + j][s] (v rows)
__device__ __nv_bfloat16 g_Wh[NROW * KDIM], g_Wl[NROW * KDIM];
__device__ __nv_bfloat16 g_Xh[(size_t)MTOK * KDIM], g_Xl[(size_t)MTOK * KDIM];
__device__ __nv_bfloat16 g_qkh[(size_t)64 * 128 * 4096];  // [hb*128+jj][s] bf16 hi (q,k)
__device__ __nv_bfloat16 g_qkl[(size_t)64 * 128 * 4096];  // bf16 lo
__device__ float         g_part[8 * 64 * 64 * 64];     // [chunk][hb][d][e] (4 used)
__device__ float         g_probs[64 * 64 * 64];        // [hb][d][e]

// ============================ split fp32 -> bf16 hi/lo ============================
__global__ void split_x(const float* __restrict__ s) {
    int idx = blockIdx.x * blockDim.x + threadIdx.x;
    float4 v = ((const float4*)s)[idx];
    __nv_bfloat162 h0 = __floats2bfloat162_rn(v.x, v.y);
    __nv_bfloat162 h1 = __floats2bfloat162_rn(v.z, v.w);
    ((__nv_bfloat162*)g_Xh)[idx * 2] = h0;
    ((__nv_bfloat162*)g_Xh)[idx * 2 + 1] = h1;
    __nv_bfloat162 l0 = __floats2bfloat162_rn(v.x - __low2float(h0), v.y - __high2float(h0));
    __nv_bfloat162 l1 = __floats2bfloat162_rn(v.z - __low2float(h1), v.w - __high2float(h1));
    ((__nv_bfloat162*)g_Xl)[idx * 2] = l0;
    ((__nv_bfloat162*)g_Xl)[idx * 2 + 1] = l1;
}
__global__ void split_w(const float* __restrict__ s) {
    int idx = blockIdx.x * blockDim.x + threadIdx.x;
    float4 v = ((const float4*)s)[idx];
    __nv_bfloat162 h0 = __floats2bfloat162_rn(v.x, v.y);
    __nv_bfloat162 h1 = __floats2bfloat162_rn(v.z, v.w);
    ((__nv_bfloat162*)g_Wh)[idx * 2] = h0;
    ((__nv_bfloat162*)g_Wh)[idx * 2 + 1] = h1;
    __nv_bfloat162 l0 = __floats2bfloat162_rn(v.x - __low2float(h0), v.y - __high2float(h0));
    __nv_bfloat162 l1 = __floats2bfloat162_rn(v.z - __low2float(h1), v.w - __high2float(h1));
    ((__nv_bfloat162*)g_Wl)[idx * 2] = l0;
    ((__nv_bfloat162*)g_Wl)[idx * 2 + 1] = l1;
}

// ============================ cp.async helpers ============================
__device__ __forceinline__ void cp16(void* dst, const void* src) {
    unsigned u = (unsigned)__cvta_generic_to_shared(dst);
    asm volatile("cp.async.cg.shared.global [%0], [%1], 16;\n" ::"r"(u), "l"(src));
}
__device__ __forceinline__ void cp_commit() { asm volatile("cp.async.commit_group;\n"); }
template <int N> __device__ __forceinline__ void cp_wait() {
    asm volatile("cp.async.wait_group %0;\n" ::"n"(N));
}

typedef wmma::fragment<wmma::matrix_a, 16, 16, 16, __nv_bfloat16, wmma::row_major> FragA;
typedef wmma::fragment<wmma::matrix_b, 16, 16, 16, __nv_bfloat16, wmma::col_major> FragB;
typedef wmma::fragment<wmma::accumulator, 16, 16, 16, float> FragC;

// ============================ QKV GEMM (R9 mainloop; epilogue: q,k -> bf16 hi/lo) ============================
#define LDM  24
#define STG  24576
#define NSTG 4

__global__ __launch_bounds__(256, 2) void qkv_gemm(const float* __restrict__ bias) {
    extern __shared__ char smem[];
    const int t = threadIdx.x;
    const int m0 = blockIdx.y * 128;
    const int tok0 = blockIdx.x * 128;

    const int row = t >> 1, half = t & 1;
    const int soff = row * LDM + half * 8;
    const size_t gA = (size_t)(m0 + row) * KDIM + half * 8;
    const size_t gB = (size_t)(tok0 + row) * KDIM + half * 8;

    auto load_stage = [&](int slot, int kt) {
        char* base = smem + slot * STG;
        const int k0 = kt * 16;
        cp16((__nv_bfloat16*)(base) + soff,         g_Wh + gA + k0);
        cp16((__nv_bfloat16*)(base + 6144) + soff,  g_Wl + gA + k0);
        cp16((__nv_bfloat16*)(base + 12288) + soff, g_Xh + gB + k0);
        cp16((__nv_bfloat16*)(base + 18432) + soff, g_Xl + gB + k0);
    };

    FragC acc[2][4];
#pragma unroll
    for (int i = 0; i < 2; i++)
#pragma unroll
        for (int j = 0; j < 4; j++) wmma::fill_fragment(acc[i][j], 0.0f);

    load_stage(0, 0); cp_commit();
    load_stage(1, 1); cp_commit();
    load_stage(2, 2); cp_commit();

    const int wid = t >> 5, lane = t & 31;
    const int wm = wid >> 1, wn = wid & 1;

    for (int kt = 0; kt < 64; kt++) {
        cp_wait<2>();
        __syncthreads();
        if (kt + 3 < 64) load_stage((kt + 3) & 3, kt + 3);
        cp_commit();

        char* base = smem + (kt & 3) * STG;
        __nv_bfloat16* sAh = (__nv_bfloat16*)(base);
        __nv_bfloat16* sAl = (__nv_bfloat16*)(base + 6144);
        __nv_bfloat16* sBh = (__nv_bfloat16*)(base + 12288);
        __nv_bfloat16* sBl = (__nv_bfloat16*)(base + 18432);

        FragA ah[2], al[2];
#pragma unroll
        for (int i = 0; i < 2; i++) {
            wmma::load_matrix_sync(ah[i], sAh + (wm * 32 + i * 16) * LDM, LDM);
            wmma::load_matrix_sync(al[i], sAl + (wm * 32 + i * 16) * LDM, LDM);
        }
#pragma unroll
        for (int j = 0; j < 4; j++) {
            FragB bh, bl;
            wmma::load_matrix_sync(bh, sBh + (wn * 64 + j * 16) * LDM, LDM);
            wmma::load_matrix_sync(bl, sBl + (wn * 64 + j * 16) * LDM, LDM);
            wmma::mma_sync(acc[0][j], ah[0], bh, acc[0][j]);
            wmma::mma_sync(acc[1][j], ah[1], bh, acc[1][j]);
            wmma::mma_sync(acc[0][j], ah[0], bl, acc[0][j]);
            wmma::mma_sync(acc[1][j], ah[1], bl, acc[1][j]);
            wmma::mma_sync(acc[0][j], al[0], bh, acc[0][j]);
            wmma::mma_sync(acc[1][j], al[1], bh, acc[1][j]);
        }
    }
    cp_wait<0>();
    __syncthreads();

    // ---- epilogue: bias + fused RoPE; q,k rows -> bf16 hi/lo, v rows -> fp32 ----
    float* sStage = (float*)smem + wid * 256;
    const int bidx = tok0 >> 12, sin = tok0 & 4095;
#pragma unroll
    for (int i = 0; i < 2; i++)
#pragma unroll
        for (int j = 0; j < 4; j++) {
            wmma::store_matrix_sync(sStage, acc[i][j], 16, wmma::mem_row_major);
            __syncwarp();
            const int m = m0 + wm * 32 + i * 16 + (lane >> 1);
            const int h = m / 192, jj = m % 192;
            const int s = sin + wn * 64 + j * 16 + ((lane & 1) << 3);
            const float bv = bias[m];
            const float* src = sStage + (lane >> 1) * 16 + ((lane & 1) << 3);
            float4 v0 = *(const float4*)src;
            float4 v1 = *(const float4*)(src + 4);
            v0.x += bv; v0.y += bv; v0.z += bv; v0.w += bv;
            v1.x += bv; v1.y += bv; v1.z += bv; v1.w += bv;
            if (sin == 0 && wn == 0 && j < 2 && jj < 128) {
                const int d = jj & 63;
                const int ibase = (j * 16 + ((lane & 1) << 3)) >> 1;
#pragma unroll
                for (int pr = 0; pr < 4; pr++) {
                    int ii = ibase + pr;
                    float inv = expf(-((float)(2 * ii) / 32.0f) * 9.210340371976184f);
                    float ang = (float)d * inv;
                    float sv, cv;
                    sincosf(ang, &sv, &cv);
                    float* pe = (pr < 2) ? ((float*)&v0 + pr * 2) : ((float*)&v1 + (pr - 2) * 2);
                    float a0 = pe[0], a1 = pe[1];
                    pe[0] = a0 * cv - a1 * sv;
                    pe[1] = a1 * cv + a0 * sv;
                }
            }
            if (jj < 128) {
                const size_t qk = (size_t)((h * 4 + bidx) * 128 + jj) * 4096 + s;
                float vv[8] = {v0.x, v0.y, v0.z, v0.w, v1.x, v1.y, v1.z, v1.w};
                alignas(16) __nv_bfloat16 hh[8];
                alignas(16) __nv_bfloat16 ll[8];
#pragma unroll
                for (int e = 0; e < 8; e++) {
                    hh[e] = __float2bfloat16(vv[e]);
                    ll[e] = __float2bfloat16(vv[e] - __bfloat162float(hh[e]));
                }
                *(uint4*)(g_qkh + qk) = *(const uint4*)hh;
                *(uint4*)(g_qkl + qk) = *(const uint4*)ll;
            } else {
                float* dst = g_qkv + (size_t)((h * 4 + bidx) * 192 + jj) * 4096 + s;
                *(float4*)dst = v0;
                *(float4*)(dst + 4) = v1;
            }
            __syncwarp();
        }
}

// ============================ scores via tensor cores (smem-staged) ============================
// g_part[cc][hb][d][e] = 0.125 * sum_{s in chunk cc} q[d][s]*k[e][s], 3-term split-bf16.
// grid (4, 64). Per block: loop 16 sub-chunks of 64 s; stage q/k hi/lo 64x64 bf16
// tiles in smem (rows padded to 72 elems -> LDSM conflict-free), double-buffered
// cp.async. 8 warps x 2 output tiles (64x64 out = 4x4 tiles of 16x16).
#define SLDM 72
#define SARR (64 * SLDM * 2)          // 9216 B per array
#define SSTG (4 * SARR)               // 36864 B per stage (qh,ql,kh,kl)

__global__ __launch_bounds__(256) void scores_tc() {
    extern __shared__ char ssm[];
    const int hb = blockIdx.y, cc = blockIdx.x;
    const int t = threadIdx.x;
    const int w = t >> 5;
    const int wi = w >> 1, wj0 = (w & 1) * 2;
    const size_t gbase = (size_t)(hb * 128) * 4096 + cc * 1024;

    // loader: 8 cp16 per thread per stage. seg idx = t + i*256, arrays:
    // 0=qh 1=ql 2=kh 3=kl; within array: row = seg>>3 (64), col8 = seg&7.
    auto load_stage = [&](int slot, int sc) {
        char* base = ssm + slot * SSTG;
        const int s0 = sc * 64;
#pragma unroll
        for (int i = 0; i < 8; i++) {
            const int idx = t + i * 256;
            const int arr = idx >> 9, seg = idx & 511;
            const int r = seg >> 3, c8 = seg & 7;
            const int grow = (arr >= 2) ? (64 + r) : r;       // k rows at +64
            const __nv_bfloat16* gsrc = ((arr & 1) ? g_qkl : g_qkh) +
                                        gbase + (size_t)grow * 4096 + s0 + c8 * 8;
            cp16((__nv_bfloat16*)(base + arr * SARR) + r * SLDM + c8 * 8, gsrc);
        }
        cp_commit();
    };

    FragC a0, a1;
    wmma::fill_fragment(a0, 0.0f);
    wmma::fill_fragment(a1, 0.0f);

    load_stage(0, 0);

    for (int sc = 0; sc < 16; sc++) {
        if (sc + 1 < 16) {
            load_stage((sc + 1) & 1, sc + 1);
            cp_wait<1>();
        } else {
            cp_wait<0>();
        }
        __syncthreads();

        char* base = ssm + (sc & 1) * SSTG;
        __nv_bfloat16* sQh = (__nv_bfloat16*)(base);
        __nv_bfloat16* sQl = (__nv_bfloat16*)(base + SARR);
        __nv_bfloat16* sKh = (__nv_bfloat16*)(base + 2 * SARR);
        __nv_bfloat16* sKl = (__nv_bfloat16*)(base + 3 * SARR);

#pragma unroll
        for (int ks = 0; ks < 4; ks++) {
            const int o = ks * 16;
            FragA qh, ql;
            FragB kh0, kl0, kh1, kl1;
            wmma::load_matrix_sync(qh, sQh + (wi * 16) * SLDM + o, SLDM);
            wmma::load_matrix_sync(ql, sQl + (wi * 16) * SLDM + o, SLDM);
            wmma::load_matrix_sync(kh0, sKh + (wj0 * 16) * SLDM + o, SLDM);
            wmma::load_matrix_sync(kl0, sKl + (wj0 * 16) * SLDM + o, SLDM);
            wmma::load_matrix_sync(kh1, sKh + ((wj0 + 1) * 16) * SLDM + o, SLDM);
            wmma::load_matrix_sync(kl1, sKl + ((wj0 + 1) * 16) * SLDM + o, SLDM);
            wmma::mma_sync(a0, qh, kh0, a0);
            wmma::mma_sync(a1, qh, kh1, a1);
            wmma::mma_sync(a0, qh, kl0, a0);
            wmma::mma_sync(a1, qh, kl1, a1);
            wmma::mma_sync(a0, ql, kh0, a0);
            wmma::mma_sync(a1, ql, kh1, a1);
        }
        __syncthreads();
    }
#pragma unroll
    for (int e = 0; e < a0.num_elements; e++) { a0.x[e] *= 0.125f; a1.x[e] *= 0.125f; }

    float* obase = g_part + ((size_t)(cc * 64 + hb) * 64 + wi * 16) * 64;
    wmma::store_matrix_sync(obase + wj0 * 16, a0, 64, wmma::mem_row_major);
    wmma::store_matrix_sync(obase + (wj0 + 1) * 16, a1, 64, wmma::mem_row_major);
}

// ============================ softmax (4 chunks) ============================
__global__ __launch_bounds__(256) void softmax_kernel() {
    int w = threadIdx.x >> 5, lane = threadIdx.x & 31;
    int r = blockIdx.x * 8 + w;  // 0..4095
    int hb = r >> 6, d = r & 63;
    float v0 = 0.f, v1 = 0.f;
#pragma unroll
    for (int c = 0; c < 4; c++) {
        const float* p = g_part + ((size_t)(c * 64 + hb) * 64 + d) * 64;
        v0 += p[lane];
        v1 += p[lane + 32];
    }
    float m = fmaxf(v0, v1);
#pragma unroll
    for (int o = 16; o > 0; o >>= 1) m = fmaxf(m, __shfl_xor_sync(0xffffffffu, m, o));
    float p0 = expf(v0 - m), p1 = expf(v1 - m);
    float sum = p0 + p1;
#pragma unroll
    for (int o = 16; o > 0; o >>= 1) sum += __shfl_xor_sync(0xffffffffu, sum, o);
    float inv = 1.0f / sum;
    float* dst = g_probs + (size_t)r * 64;
    dst[lane] = p0 * inv;
    dst[lane + 32] = p1 * inv;
}

// ============================ out GEMM (2 s-columns per thread) ============================
__global__ __launch_bounds__(256) void out_kernel(float* __restrict__ out) {
    __shared__ float sP[64 * 64];
    int hb = blockIdx.y, t = threadIdx.x;
#pragma unroll
    for (int i = 0; i < 16; i++) sP[t + 256 * i] = g_probs[(size_t)hb * 4096 + t + 256 * i];
    __syncthreads();
    int s = blockIdx.x * 256 + (t & 127);
    int dh = t >> 7;
    const float* v = g_qkv + (size_t)(hb * 192 + 128) * 4096;
    float accA[32] = {}, accB[32] = {};
    for (int e = 0; e < 64; e += 4) {
        float a0 = v[(size_t)e * 4096 + s];
        float a1 = v[(size_t)(e + 1) * 4096 + s];
        float a2 = v[(size_t)(e + 2) * 4096 + s];
        float a3 = v[(size_t)(e + 3) * 4096 + s];
        float b0 = v[(size_t)e * 4096 + s + 128];
        float b1 = v[(size_t)(e + 1) * 4096 + s + 128];
        float b2 = v[(size_t)(e + 2) * 4096 + s + 128];
        float b3 = v[(size_t)(e + 3) * 4096 + s + 128];
#pragma unroll
        for (int d = 0; d < 32; d++) {
            const float4 p = *(const float4*)&sP[(dh * 32 + d) * 64 + e];
            accA[d] += p.x * a0 + p.y * a1 + p.z * a2 + p.w * a3;
            accB[d] += p.x * b0 + p.y * b1 + p.z * b2 + p.w * b3;
        }
    }
    int h = hb >> 2, b = hb & 3;
#pragma unroll
    for (int d = 0; d < 32; d++) {
        int dd = dh * 32 + d;
        size_t o = (size_t)((h * 64 + dd) * 4 + b) * 4096 + s;
        out[o] = accA[d];
        out[o + 128] = accB[d];
    }
}

extern "C" void kernel_launch(void* const* d_in, const int* in_sizes, int n_in,
                              void* d_out, int out_size) {
    const float* x = (const float*)d_in[0];
    const float* W = (const float*)d_in[1];
    const float* bias = (const float*)d_in[2];
    float* out = (float*)d_out;

    cudaFuncSetAttribute(qkv_gemm, cudaFuncAttributeMaxDynamicSharedMemorySize, NSTG * STG);
    cudaFuncSetAttribute(scores_tc, cudaFuncAttributeMaxDynamicSharedMemorySize, 2 * SSTG);

    split_x<<<16384, 256>>>(x);                            // idx 0
    split_w<<<3072, 256>>>(W);                             // idx 1
    qkv_gemm<<<dim3(128, 24), 256, NSTG * STG>>>(bias);    // idx 2
    scores_tc<<<dim3(4, 64), 256, 2 * SSTG>>>();           // idx 3 <- ncu capture slot
    softmax_kernel<<<512, 256>>>();
    out_kernel<<<dim3(16, 64), 256>>>(out);
}